// round 4
// baseline (speedup 1.0000x reference)
#include <cuda_runtime.h>
#include <cuda_bf16.h>

// Plane2Depth: out[b,0,H,W] = 1 / max( s * (p*u + q*v + r), 0.1 )
// where [p,q,r,s] = Wmat @ feat[b,:,H/4,W/4],
//       u = ((W%4)-1.5)/4, v = ((H%4)-1.5)/4.
// (The reference's norm = sqrt(p^2+q^2+r^2+eps) cancels algebraically:
//  (p u + q v + r)/norm * s*norm == s*(p u + q v + r).)

#define IN_H   192
#define IN_W   192
#define BATCH  16
#define OUT_HW 768          // 192*4
#define PLANE  (IN_H * IN_W)

__global__ __launch_bounds__(256)
void plane2depth_kernel(const float* __restrict__ feat,
                        const float* __restrict__ Wmat,
                        float* __restrict__ out)
{
    const int W4 = IN_W / 4;                 // 48 quads per row
    int idx = blockIdx.x * 256 + threadIdx.x;
    if (idx >= BATCH * IN_H * W4) return;

    int wq = idx % W4;                       // which quad of 4 input cols
    int h  = (idx / W4) % IN_H;
    int b  = idx / (W4 * IN_H);

    // ---- load 4 input pixels (float4 per channel) ----
    const float* fp = feat + (size_t)b * 4 * PLANE + h * IN_W + wq * 4;
    float4 c0 = *(const float4*)(fp);
    float4 c1 = *(const float4*)(fp + PLANE);
    float4 c2 = *(const float4*)(fp + 2 * PLANE);
    float4 c3 = *(const float4*)(fp + 3 * PLANE);

    // ---- W matrix (uniform broadcast loads, L1-resident) ----
    float w00 = __ldg(Wmat + 0),  w01 = __ldg(Wmat + 1),  w02 = __ldg(Wmat + 2),  w03 = __ldg(Wmat + 3);
    float w10 = __ldg(Wmat + 4),  w11 = __ldg(Wmat + 5),  w12 = __ldg(Wmat + 6),  w13 = __ldg(Wmat + 7);
    float w20 = __ldg(Wmat + 8),  w21 = __ldg(Wmat + 9),  w22 = __ldg(Wmat + 10), w23 = __ldg(Wmat + 11);
    float w30 = __ldg(Wmat + 12), w31 = __ldg(Wmat + 13), w32 = __ldg(Wmat + 14), w33 = __ldg(Wmat + 15);

    float f[4][4];  // [channel][lane]
    f[0][0]=c0.x; f[0][1]=c0.y; f[0][2]=c0.z; f[0][3]=c0.w;
    f[1][0]=c1.x; f[1][1]=c1.y; f[1][2]=c1.z; f[1][3]=c1.w;
    f[2][0]=c2.x; f[2][1]=c2.y; f[2][2]=c2.z; f[2][3]=c2.w;
    f[3][0]=c3.x; f[3][1]=c3.y; f[3][2]=c3.z; f[3][3]=c3.w;

    float P[4], Q[4], R[4], S[4];
#pragma unroll
    for (int l = 0; l < 4; l++) {
        P[l] = fmaf(w00, f[0][l], fmaf(w01, f[1][l], fmaf(w02, f[2][l], w03 * f[3][l])));
        Q[l] = fmaf(w10, f[0][l], fmaf(w11, f[1][l], fmaf(w12, f[2][l], w13 * f[3][l])));
        R[l] = fmaf(w20, f[0][l], fmaf(w21, f[1][l], fmaf(w22, f[2][l], w23 * f[3][l])));
        S[l] = fmaf(w30, f[0][l], fmaf(w31, f[1][l], fmaf(w32, f[2][l], w33 * f[3][l])));
    }

    const float UV[4] = { -0.375f, -0.125f, 0.125f, 0.375f };
    const float DMIN  = 0.1f;   // 1.0 / MAX_DEPTH

    float* orow = out + (size_t)b * OUT_HW * OUT_HW + (size_t)(4 * h) * OUT_HW + (size_t)(wq * 16);

#pragma unroll
    for (int j = 0; j < 4; j++) {           // output sub-row (v index)
        float* orj = orow + (size_t)j * OUT_HW;
#pragma unroll
        for (int l = 0; l < 4; l++) {       // input pixel lane
            float base = fmaf(Q[l], UV[j], R[l]);
            float4 o;
            float d;
            d = S[l] * fmaf(P[l], UV[0], base); d = fmaxf(d, DMIN); o.x = 1.0f / d;
            d = S[l] * fmaf(P[l], UV[1], base); d = fmaxf(d, DMIN); o.y = 1.0f / d;
            d = S[l] * fmaf(P[l], UV[2], base); d = fmaxf(d, DMIN); o.z = 1.0f / d;
            d = S[l] * fmaf(P[l], UV[3], base); d = fmaxf(d, DMIN); o.w = 1.0f / d;
            *(float4*)(orj + l * 4) = o;
        }
    }
}

extern "C" void kernel_launch(void* const* d_in, const int* in_sizes, int n_in,
                              void* d_out, int out_size)
{
    const float* feat = (const float*)d_in[0];   // (16,4,192,192) f32
    const float* Wmat = (const float*)d_in[1];   // (4,4) f32
    float* out = (float*)d_out;                  // (16,1,768,768) f32

    const int threads = 256;
    const int total   = BATCH * IN_H * (IN_W / 4);   // 147456
    const int blocks  = (total + threads - 1) / threads;  // 576
    plane2depth_kernel<<<blocks, threads>>>(feat, Wmat, out);
}

// round 5
// speedup vs baseline: 1.5364x; 1.5364x over previous
#include <cuda_runtime.h>
#include <cuda_bf16.h>

// Plane2Depth: out[b,0,H,W] = 1 / max( s * (p*u + q*v + r), 0.1 )
// where [p,q,r,s] = Wmat @ feat[b,:,H/4,W/4],
//       u = ((W%4)-1.5)/4, v = ((H%4)-1.5)/4.
// (The reference's norm = sqrt(p^2+q^2+r^2+eps) cancels algebraically:
//  (p u + q v + r)/norm * s*norm == s*(p u + q v + r).)
//
// R4 layout change: ONE THREAD PER INPUT PIXEL. Lane w owns output columns
// [4w,4w+4), so every STG.128 is warp-contiguous (512B per instruction, the
// minimum 4 L1 wavefronts) instead of the previous 64B-strided pattern that
// hit 16 lines per store.

#define IN_H   192
#define IN_W   192
#define BATCH  16
#define OUT_HW 768          // 192*4
#define PLANE  (IN_H * IN_W)

__global__ __launch_bounds__(256)
void plane2depth_kernel(const float* __restrict__ feat,
                        const float* __restrict__ Wmat,
                        float* __restrict__ out)
{
    int idx = blockIdx.x * 256 + threadIdx.x;     // one input pixel
    if (idx >= BATCH * PLANE) return;

    int w = idx % IN_W;
    int h = (idx / IN_W) % IN_H;
    int b = idx / PLANE;

    // ---- load 4 channels of this pixel (each warp-coalesced 128B) ----
    const float* fp = feat + (size_t)b * 4 * PLANE + (size_t)h * IN_W + w;
    float f0 = fp[0];
    float f1 = fp[PLANE];
    float f2 = fp[2 * PLANE];
    float f3 = fp[3 * PLANE];

    // ---- W matrix (uniform broadcast loads, L1-resident) ----
    float w00 = __ldg(Wmat + 0),  w01 = __ldg(Wmat + 1),  w02 = __ldg(Wmat + 2),  w03 = __ldg(Wmat + 3);
    float w10 = __ldg(Wmat + 4),  w11 = __ldg(Wmat + 5),  w12 = __ldg(Wmat + 6),  w13 = __ldg(Wmat + 7);
    float w20 = __ldg(Wmat + 8),  w21 = __ldg(Wmat + 9),  w22 = __ldg(Wmat + 10), w23 = __ldg(Wmat + 11);
    float w30 = __ldg(Wmat + 12), w31 = __ldg(Wmat + 13), w32 = __ldg(Wmat + 14), w33 = __ldg(Wmat + 15);

    float p = fmaf(w00, f0, fmaf(w01, f1, fmaf(w02, f2, w03 * f3)));
    float q = fmaf(w10, f0, fmaf(w11, f1, fmaf(w12, f2, w13 * f3)));
    float r = fmaf(w20, f0, fmaf(w21, f1, fmaf(w22, f2, w23 * f3)));
    float s = fmaf(w30, f0, fmaf(w31, f1, fmaf(w32, f2, w33 * f3)));

    const float UV[4] = { -0.375f, -0.125f, 0.125f, 0.375f };
    const float DMIN  = 0.1f;   // 1.0 / MAX_DEPTH

    // precompute the 4 u-terms once (shared across the 4 output rows)
    float pu0 = p * UV[0], pu1 = p * UV[1], pu2 = p * UV[2], pu3 = p * UV[3];

    float* obase = out + (size_t)b * OUT_HW * OUT_HW
                       + (size_t)(4 * h) * OUT_HW
                       + (size_t)(4 * w);

#pragma unroll
    for (int j = 0; j < 4; j++) {            // output sub-row (v index)
        float base = fmaf(q, UV[j], r);
        float4 o;
        float d;
        d = s * (pu0 + base); d = fmaxf(d, DMIN); o.x = __fdividef(1.0f, d);
        d = s * (pu1 + base); d = fmaxf(d, DMIN); o.y = __fdividef(1.0f, d);
        d = s * (pu2 + base); d = fmaxf(d, DMIN); o.z = __fdividef(1.0f, d);
        d = s * (pu3 + base); d = fmaxf(d, DMIN); o.w = __fdividef(1.0f, d);
        *(float4*)(obase + (size_t)j * OUT_HW) = o;   // warp-contiguous 512B
    }
}

extern "C" void kernel_launch(void* const* d_in, const int* in_sizes, int n_in,
                              void* d_out, int out_size)
{
    const float* feat = (const float*)d_in[0];   // (16,4,192,192) f32
    const float* Wmat = (const float*)d_in[1];   // (4,4) f32
    float* out = (float*)d_out;                  // (16,1,768,768) f32

    const int threads = 256;
    const int total   = BATCH * PLANE;                    // 589824
    const int blocks  = (total + threads - 1) / threads;  // 2304
    plane2depth_kernel<<<blocks, threads>>>(feat, Wmat, out);
}